// round 12
// baseline (speedup 1.0000x reference)
#include <cuda_runtime.h>
#include <cuda_bf16.h>
#include <cstdint>
#include <cstddef>

#define MROWS 8192
#define DIN   4096
#define DOUT  4096
#define RNK   16
#define LDKX  4160
#define TK    64
#define NKC   65
#define SCALING_F 2.0f

#if defined(__CUDA_ARCH__) && (defined(__CUDA_ARCH_FEAT_SM103_ALL) || \
    defined(__CUDA_ARCH_FEAT_SM100_ALL) || defined(__CUDA_ARCH_SPECIFIC__) || \
    defined(__CUDA_ARCH_FAMILY_SPECIFIC__))
#define TC5 1
#else
#define TC5 0
#endif

// Pre-swizzled tiled layouts (byte image == SMEM image):
//   g_xh/g_xl: [mt=64][kc=65] blocks of 16384B (128 rows x 128B, SW128-permuted)
//   g_wh/g_wl: [nt=16][kc=65] blocks of 32768B (256 rows x 128B, SW128-permuted;
//              first 16KB = rows 0..127, second 16KB = rows 128..255)
__device__ __align__(128) __nv_bfloat16 g_xh[(size_t)MROWS * LDKX];
__device__ __align__(128) __nv_bfloat16 g_xl[(size_t)MROWS * LDKX];
__device__ __align__(128) __nv_bfloat16 g_wh[(size_t)DOUT * LDKX];
__device__ __align__(128) __nv_bfloat16 g_wl[(size_t)DOUT * LDKX];
__device__ __align__(128) float         g_xa[MROWS * RNK];

#define SWZ128(o) ((o) ^ (((o) >> 3) & 0x70))

__device__ __forceinline__ uint32_t smem_u32(const void* p) {
    uint32_t a;
    asm("{ .reg .u64 t; cvta.to.shared.u64 t, %1; cvt.u32.u64 %0, t; }" : "=r"(a) : "l"(p));
    return a;
}

#if TC5
__device__ __forceinline__ uint32_t elect_one() {
    uint32_t p;
    asm volatile("{\n\t.reg .pred p;\n\telect.sync _|p, 0xFFFFFFFF;\n\tselp.b32 %0, 1, 0, p;\n\t}" : "=r"(p));
    return p;
}
__device__ __forceinline__ void bulkcp(uint32_t dst, const void* src, uint32_t bytes, uint32_t mbar) {
    asm volatile(
        "cp.async.bulk.shared::cta.global.mbarrier::complete_tx::bytes [%0], [%1], %2, [%3];"
        :: "r"(dst), "l"(src), "r"(bytes), "r"(mbar) : "memory");
}
__device__ __forceinline__ void mbar_expect(uint32_t mbar, uint32_t bytes) {
    asm volatile("mbarrier.arrive.expect_tx.shared.b64 _, [%0], %1;"
                 :: "r"(mbar), "r"(bytes) : "memory");
}
__device__ __forceinline__ void mbar_wait(uint32_t mbar, uint32_t parity) {      // cta scope
    asm volatile(
        "{\n\t.reg .pred P;\n\t"
        "W_%=:\n\t"
        "mbarrier.try_wait.parity.acquire.cta.shared::cta.b64 P, [%0], %1, 0x989680;\n\t"
        "@P bra.uni D_%=;\n\t"
        "bra.uni W_%=;\n\t"
        "D_%=:\n\t}"
        :: "r"(mbar), "r"(parity) : "memory");
}
__device__ __forceinline__ void mbar_wait_cl(uint32_t mbar, uint32_t parity) {   // cluster scope
    asm volatile(
        "{\n\t.reg .pred P;\n\t"
        "W_%=:\n\t"
        "mbarrier.try_wait.parity.acquire.cluster.shared::cta.b64 P, [%0], %1, 0x989680;\n\t"
        "@P bra.uni D_%=;\n\t"
        "bra.uni W_%=;\n\t"
        "D_%=:\n\t}"
        :: "r"(mbar), "r"(parity) : "memory");
}
__device__ __forceinline__ void arrive_rank0(uint32_t addr) {
    asm volatile(
        "{\n\t.reg .b32 ra;\n\t"
        "mapa.shared::cluster.u32 ra, %0, 0;\n\t"
        "mbarrier.arrive.release.cluster.shared::cluster.b64 _, [ra];\n\t}"
        :: "r"(addr) : "memory");
}
__device__ __forceinline__ uint64_t make_desc(uint32_t addr) {   // SW128 K-major
    const uint64_t base =
        (uint64_t(2) << 61) | (uint64_t(1) << 46) | (uint64_t(64) << 32) | (uint64_t(1) << 16);
    return base | ((uint64_t)(addr >> 4) & 0x3FFFULL);
}
// cg2: bf16 in, fp32 acc, M_total=256, N=256
#define MMA_IDESC ((1u << 4) | (1u << 7) | (1u << 10) | ((256 / 8) << 17) | ((256 / 16) << 24))

__device__ __forceinline__ void mma_cg2(uint32_t d, uint64_t da, uint64_t db, uint32_t acc) {
    asm volatile(
        "{\n\t.reg .pred p;\n\t"
        "setp.ne.u32 p, %5, 0;\n\t"
        "tcgen05.mma.cta_group::2.kind::f16 [%0], %1, %2, %3, {%4,%4,%4,%4,%4,%4,%4,%4}, p;\n\t}"
        :: "r"(d), "l"(da), "l"(db), "r"(MMA_IDESC), "r"(0u), "r"(acc) : "memory");
}
__device__ __forceinline__ void ldtm32(uint32_t a, uint32_t* r) {
    asm volatile(
        "tcgen05.ld.sync.aligned.32x32b.x32.b32 "
        "{%0,%1,%2,%3,%4,%5,%6,%7,%8,%9,%10,%11,%12,%13,%14,%15,"
        "%16,%17,%18,%19,%20,%21,%22,%23,%24,%25,%26,%27,%28,%29,%30,%31}, [%32];"
        : "=r"(r[0]), "=r"(r[1]), "=r"(r[2]), "=r"(r[3]), "=r"(r[4]), "=r"(r[5]), "=r"(r[6]), "=r"(r[7]),
          "=r"(r[8]), "=r"(r[9]), "=r"(r[10]), "=r"(r[11]), "=r"(r[12]), "=r"(r[13]), "=r"(r[14]), "=r"(r[15]),
          "=r"(r[16]), "=r"(r[17]), "=r"(r[18]), "=r"(r[19]), "=r"(r[20]), "=r"(r[21]), "=r"(r[22]), "=r"(r[23]),
          "=r"(r[24]), "=r"(r[25]), "=r"(r[26]), "=r"(r[27]), "=r"(r[28]), "=r"(r[29]), "=r"(r[30]), "=r"(r[31])
        : "r"(a));
    asm volatile("tcgen05.wait::ld.sync.aligned;" ::: "memory");
}
#define CLUSTER_SYNC() do { \
    asm volatile("barrier.cluster.arrive.aligned;" ::: "memory"); \
    asm volatile("barrier.cluster.wait.aligned;" ::: "memory"); } while (0)
#endif  // TC5

// ---- kernel 1: xa = x @ A^T ----
__global__ __launch_bounds__(256) void k_xa(const float* __restrict__ x,
                                            const float* __restrict__ A) {
    __shared__ float sA[16 * 512];
    const int tid = threadIdx.x, wid = tid >> 5, lid = tid & 31;
    const int m = blockIdx.x * 8 + wid;
    float acc[RNK];
#pragma unroll
    for (int r = 0; r < RNK; r++) acc[r] = 0.f;
    for (int k0 = 0; k0 < DIN; k0 += 512) {
        __syncthreads();
        for (int i = tid; i < 2048; i += 256) {
            int r = i >> 7, k4 = i & 127;
            ((float4*)sA)[i] = *(const float4*)(A + (size_t)r * DIN + k0 + k4 * 4);
        }
        __syncthreads();
        const float4* xr = (const float4*)(x + (size_t)m * DIN + k0);
#pragma unroll
        for (int j = 0; j < 4; j++) {
            const int k4 = lid + 32 * j;
            const float4 xv = xr[k4];
#pragma unroll
            for (int r = 0; r < RNK; r++) {
                float4 av = ((const float4*)sA)[r * 128 + k4];
                acc[r] = fmaf(xv.x, av.x, acc[r]);
                acc[r] = fmaf(xv.y, av.y, acc[r]);
                acc[r] = fmaf(xv.z, av.z, acc[r]);
                acc[r] = fmaf(xv.w, av.w, acc[r]);
            }
        }
    }
#pragma unroll
    for (int r = 0; r < RNK; r++) {
        float v = acc[r];
        v += __shfl_xor_sync(0xffffffffu, v, 16);
        v += __shfl_xor_sync(0xffffffffu, v, 8);
        v += __shfl_xor_sync(0xffffffffu, v, 4);
        v += __shfl_xor_sync(0xffffffffu, v, 2);
        v += __shfl_xor_sync(0xffffffffu, v, 1);
        if (lid == 0) g_xa[m * RNK + r] = v;
    }
}

// ---- hi/lo split, writing pre-swizzled tiled layout ----
__device__ __forceinline__ void split8(const float* v, void* hdst, void* ldst) {
    uint32_t hw[4], lw[4];
#pragma unroll
    for (int k = 0; k < 4; k++) {
        __nv_bfloat16 h0 = __float2bfloat16_rn(v[2 * k]);
        __nv_bfloat16 h1 = __float2bfloat16_rn(v[2 * k + 1]);
        __nv_bfloat16 l0 = __float2bfloat16_rn(v[2 * k] - __bfloat162float(h0));
        __nv_bfloat16 l1 = __float2bfloat16_rn(v[2 * k + 1] - __bfloat162float(h1));
        hw[k] = (uint32_t)__bfloat16_as_ushort(h0) | ((uint32_t)__bfloat16_as_ushort(h1) << 16);
        lw[k] = (uint32_t)__bfloat16_as_ushort(l0) | ((uint32_t)__bfloat16_as_ushort(l1) << 16);
    }
    *(uint4*)hdst = make_uint4(hw[0], hw[1], hw[2], hw[3]);
    *(uint4*)ldst = make_uint4(lw[0], lw[1], lw[2], lw[3]);
}
__global__ __launch_bounds__(256) void k_conv_x_main(const float* __restrict__ x) {
    const int m = blockIdx.y;
    const int c0 = (blockIdx.x * 256 + threadIdx.x) * 8;   // [0,4096)
    float v[8];
    *(float4*)v       = *(const float4*)(x + (size_t)m * DIN + c0);
    *(float4*)(v + 4) = *(const float4*)(x + (size_t)m * DIN + c0 + 4);
    const size_t blk = ((size_t)(m >> 7) * NKC + (c0 >> 6)) << 14;           // 16KB blocks
    const uint32_t sw = SWZ128((uint32_t)(((m & 127) << 7) + (((c0 >> 3) & 7) << 4)));
    split8(v, (char*)g_xh + blk + sw, (char*)g_xl + blk + sw);
}
__global__ __launch_bounds__(256) void k_conv_w_main(const float* __restrict__ W) {
    const int n = blockIdx.y;
    const int c0 = (blockIdx.x * 256 + threadIdx.x) * 8;
    float v[8];
    *(float4*)v       = *(const float4*)(W + (size_t)n * DIN + c0);
    *(float4*)(v + 4) = *(const float4*)(W + (size_t)n * DIN + c0 + 4);
    const size_t blk = ((size_t)(n >> 8) * NKC + (c0 >> 6)) * 32768u;        // 32KB blocks
    const uint32_t sw = SWZ128((uint32_t)(((n & 255) << 7) + (((c0 >> 3) & 7) << 4)));
    split8(v, (char*)g_wh + blk + sw, (char*)g_wl + blk + sw);
}
__global__ __launch_bounds__(256) void k_edge_x() {
    const int idx = blockIdx.x * 256 + threadIdx.x;
    const int row = idx >> 3, seg = idx & 7;
    float v[8];
#pragma unroll
    for (int j = 0; j < 8; j++) {
        const int c = seg * 8 + j;
        v[j] = (c < RNK) ? SCALING_F * g_xa[row * RNK + c] : 0.f;
    }
    const size_t blk = ((size_t)(row >> 7) * NKC + 64) << 14;
    const uint32_t sw = SWZ128((uint32_t)(((row & 127) << 7) + (seg << 4)));
    split8(v, (char*)g_xh + blk + sw, (char*)g_xl + blk + sw);
}
__global__ __launch_bounds__(256) void k_edge_w(const float* __restrict__ lB) {
    const int idx = blockIdx.x * 256 + threadIdx.x;
    const int row = idx >> 3, seg = idx & 7;
    float v[8];
#pragma unroll
    for (int j = 0; j < 8; j++) {
        const int c = seg * 8 + j;
        v[j] = (c < RNK) ? lB[row * RNK + c] : 0.f;
    }
    const size_t blk = ((size_t)(row >> 8) * NKC + 64) * 32768u;
    const uint32_t sw = SWZ128((uint32_t)(((row & 255) << 7) + (seg << 4)));
    split8(v, (char*)g_wh + blk + sw, (char*)g_wl + blk + sw);
}

// ---- main GEMM: cg2 256x256 cluster tile, 3-stage 64KB bulk-copy pipeline ----
// SMEM: [0] tmem ptr; full[3]@16/24/32; done[3]@40/48/56; peerrdy[3]@64/72/80;
//       bias@1024; stages@2048 (3 x 65536)
#define SMEM_BIAS   1024
#define SMEM_STAGE0 2048
#define STAGE_BYTES 65536
#define OFF_AH 0
#define OFF_AL 16384
#define OFF_BH 32768
#define OFF_BL 49152
#define SMEM_TOTAL (SMEM_STAGE0 + 3 * STAGE_BYTES)

__global__ __launch_bounds__(256, 1) __cluster_dims__(2, 1, 1)
void k_gemm(const float* __restrict__ bias, float* __restrict__ out,
            const float* __restrict__ x, const float* __restrict__ W,
            const float* __restrict__ lB) {
    extern __shared__ char smem[];
    const int tid = threadIdx.x;
    const int rank = blockIdx.x;                   // cluster rank
    const int n0 = blockIdx.y * 256;
    const int mb = blockIdx.z * 256 + rank * 128;  // this CTA's 128 M rows
#if TC5
    const uint32_t sbase = smem_u32(smem);
    const int wid = tid >> 5, lid = tid & 31;
    const uint32_t FUL = sbase + 16, DON = sbase + 40, RDY = sbase + 64;

    if (wid == 0) {
        asm volatile("tcgen05.alloc.cta_group::2.sync.aligned.shared::cta.b32 [%0], %1;"
                     :: "r"(sbase), "r"(256u) : "memory");
        asm volatile("tcgen05.relinquish_alloc_permit.cta_group::2.sync.aligned;");
    }
    if (tid < 9)
        asm volatile("mbarrier.init.shared.b64 [%0], 1;" :: "r"(sbase + 16 + tid * 8) : "memory");
    ((float*)(smem + SMEM_BIAS))[tid] = bias[n0 + tid];
    __syncthreads();
    CLUSTER_SYNC();    // all mbars live before any cross-CTA arrive / multicast commit
    uint32_t tmem;
    asm volatile("ld.shared.b32 %0, [%1];" : "=r"(tmem) : "r"(sbase));

    if (wid == 0 && elect_one()) {
        // this CTA's own slices (A: its 128 M-rows; B: its 128 N-rows)
        const char* xh_t = (char*)g_xh + ((size_t)(mb >> 7) * NKC << 14);
        const char* xl_t = (char*)g_xl + ((size_t)(mb >> 7) * NKC << 14);
        const char* wh_t = (char*)g_wh + ((size_t)(n0 >> 8) * NKC) * 32768u + (size_t)rank * 16384u;
        const char* wl_t = (char*)g_wl + ((size_t)(n0 >> 8) * NKC) * 32768u + (size_t)rank * 16384u;

#pragma unroll
        for (int p = 0; p < 2; p++) {      // prologue: chunks 0,1 -> stages 0,1
            const uint32_t st = sbase + SMEM_STAGE0 + p * STAGE_BYTES;
            const uint32_t fm = FUL + p * 8;
            mbar_expect(fm, STAGE_BYTES);
            bulkcp(st + OFF_AH, xh_t + ((size_t)p << 14), 16384u, fm);
            bulkcp(st + OFF_AL, xl_t + ((size_t)p << 14), 16384u, fm);
            bulkcp(st + OFF_BH, wh_t + ((size_t)p << 15), 16384u, fm);
            bulkcp(st + OFF_BL, wl_t + ((size_t)p << 15), 16384u, fm);
        }

#pragma unroll 1
        for (int kt = 0; kt < NKC; kt++) {
            const int s = kt % 3;
            const uint32_t ph = (uint32_t)((kt / 3) & 1);
            if (kt + 2 < NKC) {            // load chunk kt+2 into stage (kt+2)%3
                const int sl = (kt + 2) % 3;
                if (kt >= 1)               // prior occupant: chunk kt-1 (same slot)
                    mbar_wait_cl(DON + sl * 8, (uint32_t)(((kt - 1) / 3) & 1));
                const uint32_t st = sbase + SMEM_STAGE0 + sl * STAGE_BYTES;
                const uint32_t fm = FUL + sl * 8;
                const size_t kb14 = (size_t)(kt + 2) << 14;
                const size_t kb15 = (size_t)(kt + 2) << 15;
                mbar_expect(fm, STAGE_BYTES);
                bulkcp(st + OFF_AH, xh_t + kb14, 16384u, fm);
                bulkcp(st + OFF_AL, xl_t + kb14, 16384u, fm);
                bulkcp(st + OFF_BH, wh_t + kb15, 16384u, fm);
                bulkcp(st + OFF_BL, wl_t + kb15, 16384u, fm);
            }
            mbar_wait(FUL + s * 8, ph);    // own stage data landed

            if (rank == 0) {
                mbar_wait_cl(RDY + s * 8, ph);   // peer stage landed (pre-arrived)
                const uint32_t st = sbase + SMEM_STAGE0 + s * STAGE_BYTES;
                const uint64_t dAH = make_desc(st + OFF_AH);
                const uint64_t dAL = make_desc(st + OFF_AL);
                const uint64_t dBH = make_desc(st + OFF_BH);
                const uint64_t dBL = make_desc(st + OFF_BL);
#pragma unroll
                for (int ks = 0; ks < 4; ks++)
                    mma_cg2(tmem, dAH + 2 * ks, dBH + 2 * ks, (kt == 0 && ks == 0) ? 0u : 1u);
#pragma unroll
                for (int ks = 0; ks < 4; ks++)
                    mma_cg2(tmem, dAH + 2 * ks, dBL + 2 * ks, 1u);
#pragma unroll
                for (int ks = 0; ks < 4; ks++)
                    mma_cg2(tmem, dAL + 2 * ks, dBH + 2 * ks, 1u);
                asm volatile(
                    "tcgen05.commit.cta_group::2.mbarrier::arrive::one.shared::cluster.multicast::cluster.b64 [%0], %1;"
                    :: "r"(DON + s * 8), "h"((uint16_t)0x3) : "memory");
            } else {
                arrive_rank0(RDY + s * 8);       // my stage s is loaded
            }
        }
        // last chunk 64: stage 64%3=1, phase (64/3)&1=1
        mbar_wait_cl(DON + 8, 1u);
    }
    __syncthreads();
    asm volatile("tcgen05.fence::after_thread_sync;" ::: "memory");

    const float* sbf = (const float*)(smem + SMEM_BIAS);
    const int rw = wid & 3, ch = wid >> 2;       // 8 warps: 4 row-groups x 2 col-halves
    float* orow = out + (size_t)(mb + rw * 32 + lid) * DOUT + n0 + ch * 128;
#pragma unroll 1
    for (int c0 = 0; c0 < 128; c0 += 32) {
        uint32_t r[32];
        ldtm32(tmem + ch * 128 + c0, r);
#pragma unroll
        for (int j = 0; j < 32; j += 4) {
            float4 v;
            v.x = __uint_as_float(r[j + 0]) + sbf[ch * 128 + c0 + j + 0];
            v.y = __uint_as_float(r[j + 1]) + sbf[ch * 128 + c0 + j + 1];
            v.z = __uint_as_float(r[j + 2]) + sbf[ch * 128 + c0 + j + 2];
            v.w = __uint_as_float(r[j + 3]) + sbf[ch * 128 + c0 + j + 3];
            *(float4*)(orow + c0 + j) = v;
        }
    }
    __syncthreads();
    CLUSTER_SYNC();    // no CTA may exit/dealloc while peer MMA state could reference it
    if (wid == 0) {
        asm volatile("tcgen05.dealloc.cta_group::2.sync.aligned.b32 %0, %1;"
                     :: "r"(tmem), "r"(256u));
    }
    CLUSTER_SYNC();
#else
    // ---------- fp32 SIMT fallback (base sm_103 target) ----------
    float* As = (float*)smem;            // [128][17]
    float* Bs = As + 128 * 17;           // [128][17]
    const int tx = tid & 15, ty = tid >> 4;
#pragma unroll 1
    for (int nh = 0; nh < 2; nh++) {
        const int nb = n0 + nh * 128;
        float acc[8][8];
#pragma unroll
        for (int i = 0; i < 8; i++)
#pragma unroll
            for (int j = 0; j < 8; j++) acc[i][j] = 0.f;
#pragma unroll 1
        for (int k0 = 0; k0 < DIN; k0 += 16) {
            __syncthreads();
            for (int i = tid; i < 128 * 16; i += 256) {
                const int m = i >> 4, kk = i & 15;
                As[m * 17 + kk] = x[(size_t)(mb + m) * DIN + k0 + kk];
                Bs[m * 17 + kk] = W[(size_t)(nb + m) * DIN + k0 + kk];
            }
            __syncthreads();
#pragma unroll
            for (int kk = 0; kk < 16; kk++) {
                float ra[8], rb[8];
#pragma unroll
                for (int j = 0; j < 8; j++) {
                    ra[j] = As[(ty * 8 + j) * 17 + kk];
                    rb[j] = Bs[(tx * 8 + j) * 17 + kk];
                }
#pragma unroll
                for (int i = 0; i < 8; i++)
#pragma unroll
                    for (int j = 0; j < 8; j++)
                        acc[i][j] = fmaf(ra[i], rb[j], acc[i][j]);
            }
        }
#pragma unroll
        for (int i = 0; i < 8; i++) {
            const int m = mb + ty * 8 + i;
            const float* xar = g_xa + m * RNK;
#pragma unroll
            for (int j = 0; j < 8; j++) {
                const int n = nb + tx * 8 + j;
                float l = 0.f;
#pragma unroll
                for (int r = 0; r < RNK; r++) l = fmaf(xar[r], lB[n * RNK + r], l);
                out[(size_t)m * DOUT + n] = acc[i][j] + bias[n] + SCALING_F * l;
            }
        }
        __syncthreads();
    }
#endif
}

extern "C" void kernel_launch(void* const* d_in, const int* in_sizes, int n_in,
                              void* d_out, int out_size) {
    const float* x  = (const float*)d_in[0];
    const float* W  = (const float*)d_in[1];
    const float* b  = (const float*)d_in[2];
    const float* lA = (const float*)d_in[3];
    const float* lB = (const float*)d_in[4];
    float* out = (float*)d_out;

    cudaFuncSetAttribute(k_gemm, cudaFuncAttributeMaxDynamicSharedMemorySize, SMEM_TOTAL);

    k_xa<<<MROWS / 8, 256>>>(x, lA);
    k_conv_x_main<<<dim3(DIN / 2048, MROWS), 256>>>(x);
    k_conv_w_main<<<dim3(DIN / 2048, DOUT), 256>>>(W);
    k_edge_x<<<MROWS * 8 / 256, 256>>>();
    k_edge_w<<<DOUT * 8 / 256, 256>>>(lB);
    // grid: (rank 2) x (16 n-tiles) x (32 m-pairs) = 1024 CTAs, 512 clusters
    k_gemm<<<dim3(2, DOUT / 256, MROWS / 256), 256, SMEM_TOTAL>>>(b, out, x, W, lB);
}

// round 13
// speedup vs baseline: 1.5520x; 1.5520x over previous
#include <cuda_runtime.h>
#include <cuda_bf16.h>
#include <cstdint>
#include <cstddef>

#define MROWS 8192
#define DIN   4096
#define DOUT  4096
#define RNK   16
#define LDKX  4160
#define TM    128
#define TN    256
#define TK    64
#define NKC   65
#define SCALING_F 2.0f

#if defined(__CUDA_ARCH__) && (defined(__CUDA_ARCH_FEAT_SM103_ALL) || \
    defined(__CUDA_ARCH_FEAT_SM100_ALL) || defined(__CUDA_ARCH_SPECIFIC__) || \
    defined(__CUDA_ARCH_FAMILY_SPECIFIC__))
#define TC5 1
#else
#define TC5 0
#endif

// Pre-swizzled tiled layouts (byte image == SMEM image):
//   g_xh/g_xl: [mt=64][kc=65] blocks of 16384B (128 rows x 128B, SW128-permuted)
//   g_wh/g_wl: [nt=16][kc=65] blocks of 32768B (256 rows x 128B, SW128-permuted)
__device__ __align__(128) __nv_bfloat16 g_xh[(size_t)MROWS * LDKX];
__device__ __align__(128) __nv_bfloat16 g_xl[(size_t)MROWS * LDKX];
__device__ __align__(128) __nv_bfloat16 g_wh[(size_t)DOUT * LDKX];
__device__ __align__(128) __nv_bfloat16 g_wl[(size_t)DOUT * LDKX];
__device__ __align__(128) float         g_xa[MROWS * RNK];

#define SWZ128(o) ((o) ^ (((o) >> 3) & 0x70))

__device__ __forceinline__ uint32_t smem_u32(const void* p) {
    uint32_t a;
    asm("{ .reg .u64 t; cvta.to.shared.u64 t, %1; cvt.u32.u64 %0, t; }" : "=r"(a) : "l"(p));
    return a;
}

#if TC5
__device__ __forceinline__ uint32_t elect_one() {
    uint32_t p;
    asm volatile("{\n\t.reg .pred p;\n\telect.sync _|p, 0xFFFFFFFF;\n\tselp.b32 %0, 1, 0, p;\n\t}" : "=r"(p));
    return p;
}
__device__ __forceinline__ void bulkcp(uint32_t dst, const void* src, uint32_t bytes, uint32_t mbar) {
    asm volatile(
        "cp.async.bulk.shared::cta.global.mbarrier::complete_tx::bytes [%0], [%1], %2, [%3];"
        :: "r"(dst), "l"(src), "r"(bytes), "r"(mbar) : "memory");
}
// 1D bulk multicast: delivers `bytes` + complete_tx to same SMEM offset in every CTA in mask
__device__ __forceinline__ void bulkcp_mc(uint32_t dst, const void* src, uint32_t bytes,
                                          uint32_t mbar, uint16_t mask) {
    asm volatile(
        "cp.async.bulk.shared::cluster.global.mbarrier::complete_tx::bytes.multicast::cluster "
        "[%0], [%1], %2, [%3], %4;"
        :: "r"(dst), "l"(src), "r"(bytes), "r"(mbar), "h"(mask) : "memory");
}
__device__ __forceinline__ void mbar_expect(uint32_t mbar, uint32_t bytes) {
    asm volatile("mbarrier.arrive.expect_tx.shared.b64 _, [%0], %1;"
                 :: "r"(mbar), "r"(bytes) : "memory");
}
__device__ __forceinline__ void mbar_wait(uint32_t mbar, uint32_t parity) {      // cta scope
    asm volatile(
        "{\n\t.reg .pred P;\n\t"
        "W_%=:\n\t"
        "mbarrier.try_wait.parity.acquire.cta.shared::cta.b64 P, [%0], %1, 0x989680;\n\t"
        "@P bra.uni D_%=;\n\t"
        "bra.uni W_%=;\n\t"
        "D_%=:\n\t}"
        :: "r"(mbar), "r"(parity) : "memory");
}
__device__ __forceinline__ void mbar_wait_cl(uint32_t mbar, uint32_t parity) {   // cluster scope
    asm volatile(
        "{\n\t.reg .pred P;\n\t"
        "W_%=:\n\t"
        "mbarrier.try_wait.parity.acquire.cluster.shared::cta.b64 P, [%0], %1, 0x989680;\n\t"
        "@P bra.uni D_%=;\n\t"
        "bra.uni W_%=;\n\t"
        "D_%=:\n\t}"
        :: "r"(mbar), "r"(parity) : "memory");
}
__device__ __forceinline__ uint64_t make_desc(uint32_t addr) {   // SW128 K-major
    const uint64_t base =
        (uint64_t(2) << 61) | (uint64_t(1) << 46) | (uint64_t(64) << 32) | (uint64_t(1) << 16);
    return base | ((uint64_t)(addr >> 4) & 0x3FFFULL);
}
// cg1: bf16 in, fp32 acc, M=128, N=256
#define MMA_IDESC ((1u << 4) | (1u << 7) | (1u << 10) | ((TN / 8) << 17) | ((TM / 16) << 24))

__device__ __forceinline__ void mma_ss(uint32_t d, uint64_t da, uint64_t db, uint32_t acc) {
    asm volatile(
        "{\n\t.reg .pred p;\n\t"
        "setp.ne.u32 p, %5, 0;\n\t"
        "tcgen05.mma.cta_group::1.kind::f16 [%0], %1, %2, %3, {%4, %4, %4, %4}, p;\n\t}"
        :: "r"(d), "l"(da), "l"(db), "r"(MMA_IDESC), "r"(0u), "r"(acc) : "memory");
}
__device__ __forceinline__ void ldtm32(uint32_t a, uint32_t* r) {
    asm volatile(
        "tcgen05.ld.sync.aligned.32x32b.x32.b32 "
        "{%0,%1,%2,%3,%4,%5,%6,%7,%8,%9,%10,%11,%12,%13,%14,%15,"
        "%16,%17,%18,%19,%20,%21,%22,%23,%24,%25,%26,%27,%28,%29,%30,%31}, [%32];"
        : "=r"(r[0]), "=r"(r[1]), "=r"(r[2]), "=r"(r[3]), "=r"(r[4]), "=r"(r[5]), "=r"(r[6]), "=r"(r[7]),
          "=r"(r[8]), "=r"(r[9]), "=r"(r[10]), "=r"(r[11]), "=r"(r[12]), "=r"(r[13]), "=r"(r[14]), "=r"(r[15]),
          "=r"(r[16]), "=r"(r[17]), "=r"(r[18]), "=r"(r[19]), "=r"(r[20]), "=r"(r[21]), "=r"(r[22]), "=r"(r[23]),
          "=r"(r[24]), "=r"(r[25]), "=r"(r[26]), "=r"(r[27]), "=r"(r[28]), "=r"(r[29]), "=r"(r[30]), "=r"(r[31])
        : "r"(a));
    asm volatile("tcgen05.wait::ld.sync.aligned;" ::: "memory");
}
#define CLUSTER_SYNC() do { \
    asm volatile("barrier.cluster.arrive.aligned;" ::: "memory"); \
    asm volatile("barrier.cluster.wait.aligned;" ::: "memory"); } while (0)
#endif  // TC5

// ---- kernel 1: xa = x @ A^T ----
__global__ __launch_bounds__(256) void k_xa(const float* __restrict__ x,
                                            const float* __restrict__ A) {
    __shared__ float sA[16 * 512];
    const int tid = threadIdx.x, wid = tid >> 5, lid = tid & 31;
    const int m = blockIdx.x * 8 + wid;
    float acc[RNK];
#pragma unroll
    for (int r = 0; r < RNK; r++) acc[r] = 0.f;
    for (int k0 = 0; k0 < DIN; k0 += 512) {
        __syncthreads();
        for (int i = tid; i < 2048; i += 256) {
            int r = i >> 7, k4 = i & 127;
            ((float4*)sA)[i] = *(const float4*)(A + (size_t)r * DIN + k0 + k4 * 4);
        }
        __syncthreads();
        const float4* xr = (const float4*)(x + (size_t)m * DIN + k0);
#pragma unroll
        for (int j = 0; j < 4; j++) {
            const int k4 = lid + 32 * j;
            const float4 xv = xr[k4];
#pragma unroll
            for (int r = 0; r < RNK; r++) {
                float4 av = ((const float4*)sA)[r * 128 + k4];
                acc[r] = fmaf(xv.x, av.x, acc[r]);
                acc[r] = fmaf(xv.y, av.y, acc[r]);
                acc[r] = fmaf(xv.z, av.z, acc[r]);
                acc[r] = fmaf(xv.w, av.w, acc[r]);
            }
        }
    }
#pragma unroll
    for (int r = 0; r < RNK; r++) {
        float v = acc[r];
        v += __shfl_xor_sync(0xffffffffu, v, 16);
        v += __shfl_xor_sync(0xffffffffu, v, 8);
        v += __shfl_xor_sync(0xffffffffu, v, 4);
        v += __shfl_xor_sync(0xffffffffu, v, 2);
        v += __shfl_xor_sync(0xffffffffu, v, 1);
        if (lid == 0) g_xa[m * RNK + r] = v;
    }
}

// ---- hi/lo split, writing pre-swizzled tiled layout ----
__device__ __forceinline__ void split8(const float* v, void* hdst, void* ldst) {
    uint32_t hw[4], lw[4];
#pragma unroll
    for (int k = 0; k < 4; k++) {
        __nv_bfloat16 h0 = __float2bfloat16_rn(v[2 * k]);
        __nv_bfloat16 h1 = __float2bfloat16_rn(v[2 * k + 1]);
        __nv_bfloat16 l0 = __float2bfloat16_rn(v[2 * k] - __bfloat162float(h0));
        __nv_bfloat16 l1 = __float2bfloat16_rn(v[2 * k + 1] - __bfloat162float(h1));
        hw[k] = (uint32_t)__bfloat16_as_ushort(h0) | ((uint32_t)__bfloat16_as_ushort(h1) << 16);
        lw[k] = (uint32_t)__bfloat16_as_ushort(l0) | ((uint32_t)__bfloat16_as_ushort(l1) << 16);
    }
    *(uint4*)hdst = make_uint4(hw[0], hw[1], hw[2], hw[3]);
    *(uint4*)ldst = make_uint4(lw[0], lw[1], lw[2], lw[3]);
}
__global__ __launch_bounds__(256) void k_conv_x_main(const float* __restrict__ x) {
    const int m = blockIdx.y;
    const int c0 = (blockIdx.x * 256 + threadIdx.x) * 8;   // [0,4096)
    float v[8];
    *(float4*)v       = *(const float4*)(x + (size_t)m * DIN + c0);
    *(float4*)(v + 4) = *(const float4*)(x + (size_t)m * DIN + c0 + 4);
    const size_t blk = ((size_t)(m >> 7) * NKC + (c0 >> 6)) << 14;           // 16KB blocks
    const uint32_t sw = SWZ128((uint32_t)(((m & 127) << 7) + (((c0 >> 3) & 7) << 4)));
    split8(v, (char*)g_xh + blk + sw, (char*)g_xl + blk + sw);
}
__global__ __launch_bounds__(256) void k_conv_w_main(const float* __restrict__ W) {
    const int n = blockIdx.y;
    const int c0 = (blockIdx.x * 256 + threadIdx.x) * 8;
    float v[8];
    *(float4*)v       = *(const float4*)(W + (size_t)n * DIN + c0);
    *(float4*)(v + 4) = *(const float4*)(W + (size_t)n * DIN + c0 + 4);
    const size_t blk = ((size_t)(n >> 8) * NKC + (c0 >> 6)) * 32768u;        // 32KB blocks
    const uint32_t sw = SWZ128((uint32_t)(((n & 255) << 7) + (((c0 >> 3) & 7) << 4)));
    split8(v, (char*)g_wh + blk + sw, (char*)g_wl + blk + sw);
}
__global__ __launch_bounds__(256) void k_edge_x() {
    const int idx = blockIdx.x * 256 + threadIdx.x;
    const int row = idx >> 3, seg = idx & 7;
    float v[8];
#pragma unroll
    for (int j = 0; j < 8; j++) {
        const int c = seg * 8 + j;
        v[j] = (c < RNK) ? SCALING_F * g_xa[row * RNK + c] : 0.f;
    }
    const size_t blk = ((size_t)(row >> 7) * NKC + 64) << 14;
    const uint32_t sw = SWZ128((uint32_t)(((row & 127) << 7) + (seg << 4)));
    split8(v, (char*)g_xh + blk + sw, (char*)g_xl + blk + sw);
}
__global__ __launch_bounds__(256) void k_edge_w(const float* __restrict__ lB) {
    const int idx = blockIdx.x * 256 + threadIdx.x;
    const int row = idx >> 3, seg = idx & 7;
    float v[8];
#pragma unroll
    for (int j = 0; j < 8; j++) {
        const int c = seg * 8 + j;
        v[j] = (c < RNK) ? lB[row * RNK + c] : 0.f;
    }
    const size_t blk = ((size_t)(row >> 8) * NKC + 64) * 32768u;
    const uint32_t sw = SWZ128((uint32_t)(((row & 255) << 7) + (seg << 4)));
    split8(v, (char*)g_wh + blk + sw, (char*)g_wl + blk + sw);
}

// ---- main GEMM: cg1 engine (R10), B transported once per cluster via multicast ----
// Cluster(2): both ranks share n0; m differs by 128. MMAs are per-CTA cg1 (local SMEM only).
// SMEM: [0] tmem ptr; full[2]@16/24 (count 1); done[2]@32/40 (count 2 = both ranks' commits);
//       bias@1024; stages@2048 (2 x 98304)
#define SMEM_BIAS   1024
#define SMEM_STAGE0 2048
#define STAGE_BYTES 98304
#define OFF_AH 0
#define OFF_AL 16384
#define OFF_BH 32768
#define OFF_BL 65536
#define SMEM_TOTAL (SMEM_STAGE0 + 2 * STAGE_BYTES)

__global__ __launch_bounds__(256, 1) __cluster_dims__(2, 1, 1)
void k_gemm(const float* __restrict__ bias, float* __restrict__ out,
            const float* __restrict__ x, const float* __restrict__ W,
            const float* __restrict__ lB) {
    extern __shared__ char smem[];
    const int tid = threadIdx.x;
    const int rank = blockIdx.x;                    // cluster rank
    const int n0 = blockIdx.y * TN;
    const int m0 = blockIdx.z * 256 + rank * TM;    // this CTA's 128 M rows
#if TC5
    const uint32_t sbase = smem_u32(smem);
    const int wid = tid >> 5, lid = tid & 31;
    const uint32_t FUL = sbase + 16, DON = sbase + 32;

    if (wid == 0) {
        asm volatile("tcgen05.alloc.cta_group::1.sync.aligned.shared::cta.b32 [%0], %1;"
                     :: "r"(sbase), "r"(256u) : "memory");
        asm volatile("tcgen05.relinquish_alloc_permit.cta_group::1.sync.aligned;");
    }
    if (tid < 2)
        asm volatile("mbarrier.init.shared.b64 [%0], 1;" :: "r"(FUL + tid * 8) : "memory");
    else if (tid < 4)
        asm volatile("mbarrier.init.shared.b64 [%0], 2;" :: "r"(DON + (tid - 2) * 8) : "memory");
    ((float*)(smem + SMEM_BIAS))[tid] = bias[n0 + tid];
    __syncthreads();
    CLUSTER_SYNC();    // all mbars live before any multicast targets them
    uint32_t tmem;
    asm volatile("ld.shared.b32 %0, [%1];" : "=r"(tmem) : "r"(sbase));

    if (wid == 0 && elect_one()) {
        const char* xh_t = (char*)g_xh + ((size_t)(m0 >> 7) * NKC << 14);
        const char* xl_t = (char*)g_xl + ((size_t)(m0 >> 7) * NKC << 14);
        const char* wh_t = (char*)g_wh + ((size_t)(n0 >> 8) * NKC) * 32768u;
        const char* wl_t = (char*)g_wl + ((size_t)(n0 >> 8) * NKC) * 32768u;

        // prologue: chunk 0 -> stage 0 (A per-CTA; B multicast by rank 0)
        {
            const uint32_t st = sbase + SMEM_STAGE0;
            mbar_expect(FUL, STAGE_BYTES);
            bulkcp(st + OFF_AH, xh_t, 16384u, FUL);
            bulkcp(st + OFF_AL, xl_t, 16384u, FUL);
            if (rank == 0) {
                bulkcp_mc(st + OFF_BH, wh_t, 32768u, FUL, (uint16_t)0x3);
                bulkcp_mc(st + OFF_BL, wl_t, 32768u, FUL, (uint16_t)0x3);
            }
        }
#pragma unroll 1
        for (int kt = 0; kt < NKC; kt++) {
            const int s = kt & 1;
            if (kt + 1 < NKC) {
                const int sn = s ^ 1;
                if (kt >= 1)   // stage sn last used by chunk kt-1: BOTH ranks' MMAs must drain
                    mbar_wait_cl(DON + sn * 8, (uint32_t)(((kt - 1) >> 1) & 1));
                const uint32_t st = sbase + SMEM_STAGE0 + sn * STAGE_BYTES;
                const uint32_t fm = FUL + sn * 8;
                const size_t kb16 = (size_t)(kt + 1) << 14;
                const size_t kb32 = (size_t)(kt + 1) << 15;
                mbar_expect(fm, STAGE_BYTES);
                bulkcp(st + OFF_AH, xh_t + kb16, 16384u, fm);
                bulkcp(st + OFF_AL, xl_t + kb16, 16384u, fm);
                if (rank == 0) {
                    bulkcp_mc(st + OFF_BH, wh_t + kb32, 32768u, fm, (uint16_t)0x3);
                    bulkcp_mc(st + OFF_BL, wl_t + kb32, 32768u, fm, (uint16_t)0x3);
                }
            }
            mbar_wait(FUL + s * 8, (uint32_t)((kt >> 1) & 1));   // data landed (A own + B mc)

            const uint32_t st = sbase + SMEM_STAGE0 + s * STAGE_BYTES;
            const uint64_t dAH = make_desc(st + OFF_AH);
            const uint64_t dAL = make_desc(st + OFF_AL);
            const uint64_t dBH = make_desc(st + OFF_BH);
            const uint64_t dBL = make_desc(st + OFF_BL);
#pragma unroll
            for (int ks = 0; ks < 4; ks++)
                mma_ss(tmem, dAH + 2 * ks, dBH + 2 * ks, (kt == 0 && ks == 0) ? 0u : 1u);
#pragma unroll
            for (int ks = 0; ks < 4; ks++)
                mma_ss(tmem, dAH + 2 * ks, dBL + 2 * ks, 1u);
#pragma unroll
            for (int ks = 0; ks < 4; ks++)
                mma_ss(tmem, dAL + 2 * ks, dBH + 2 * ks, 1u);
            // commit to done[s] in BOTH CTAs (peer needs it before overwriting its stage:
            // rank0's B-multicast writes peer SMEM; rank1's A-issue gates likewise)
            asm volatile(
                "tcgen05.commit.cta_group::1.mbarrier::arrive::one.shared::cluster.multicast::cluster.b64 [%0], %1;"
                :: "r"(DON + s * 8), "h"((uint16_t)0x3) : "memory");
        }
        // chunk 64 on stage 0: 33rd phase -> parity (64>>1)&1 = 0
        mbar_wait_cl(DON, 0u);
    }
    __syncthreads();
    asm volatile("tcgen05.fence::after_thread_sync;" ::: "memory");

    const float* sbf = (const float*)(smem + SMEM_BIAS);
    const int rw = wid & 3, ch = wid >> 2;      // 8 warps: 4 row-groups x 2 col-halves
    float* orow = out + (size_t)(m0 + rw * 32 + lid) * DOUT + n0 + ch * 128;
#pragma unroll 1
    for (int c0 = 0; c0 < 128; c0 += 32) {
        uint32_t r[32];
        ldtm32(tmem + ch * 128 + c0, r);
#pragma unroll
        for (int j = 0; j < 32; j += 4) {
            float4 v;
            v.x = __uint_as_float(r[j + 0]) + sbf[ch * 128 + c0 + j + 0];
            v.y = __uint_as_float(r[j + 1]) + sbf[ch * 128 + c0 + j + 1];
            v.z = __uint_as_float(r[j + 2]) + sbf[ch * 128 + c0 + j + 2];
            v.w = __uint_as_float(r[j + 3]) + sbf[ch * 128 + c0 + j + 3];
            *(float4*)(orow + c0 + j) = v;
        }
    }
    __syncthreads();
    if (wid == 0)
        asm volatile("tcgen05.dealloc.cta_group::1.sync.aligned.b32 %0, %1;"
                     :: "r"(tmem), "r"(256u));
    CLUSTER_SYNC();   // no CTA exits while peer multicast/commit may target its SMEM
#else
    // ---------- fp32 SIMT fallback (base sm_103 target) ----------
    float* As = (float*)smem;            // [128][17]
    float* Bs = As + 128 * 17;           // [128][17]
    const int tx = tid & 15, ty = tid >> 4;
#pragma unroll 1
    for (int nh = 0; nh < 2; nh++) {
        const int nb = n0 + nh * 128;
        float acc[8][8];
#pragma unroll
        for (int i = 0; i < 8; i++)
#pragma unroll
            for (int j = 0; j < 8; j++) acc[i][j] = 0.f;
#pragma unroll 1
        for (int k0 = 0; k0 < DIN; k0 += 16) {
            __syncthreads();
            for (int i = tid; i < 128 * 16; i += 256) {
                const int m = i >> 4, kk = i & 15;
                As[m * 17 + kk] = x[(size_t)(m0 + m) * DIN + k0 + kk];
                Bs[m * 17 + kk] = W[(size_t)(nb + m) * DIN + k0 + kk];
            }
            __syncthreads();
#pragma unroll
            for (int kk = 0; kk < 16; kk++) {
                float ra[8], rb[8];
#pragma unroll
                for (int j = 0; j < 8; j++) {
                    ra[j] = As[(ty * 8 + j) * 17 + kk];
                    rb[j] = Bs[(tx * 8 + j) * 17 + kk];
                }
#pragma unroll
                for (int i = 0; i < 8; i++)
#pragma unroll
                    for (int j = 0; j < 8; j++)
                        acc[i][j] = fmaf(ra[i], rb[j], acc[i][j]);
            }
        }
#pragma unroll
        for (int i = 0; i < 8; i++) {
            const int m = m0 + ty * 8 + i;
            const float* xar = g_xa + m * RNK;
#pragma unroll
            for (int j = 0; j < 8; j++) {
                const int n = nb + tx * 8 + j;
                float l = 0.f;
#pragma unroll
                for (int r = 0; r < RNK; r++) l = fmaf(xar[r], lB[n * RNK + r], l);
                out[(size_t)m * DOUT + n] = acc[i][j] + bias[n] + SCALING_F * l;
            }
        }
        __syncthreads();
    }
#endif
}

extern "C" void kernel_launch(void* const* d_in, const int* in_sizes, int n_in,
                              void* d_out, int out_size) {
    const float* x  = (const float*)d_in[0];
    const float* W  = (const float*)d_in[1];
    const float* b  = (const float*)d_in[2];
    const float* lA = (const float*)d_in[3];
    const float* lB = (const float*)d_in[4];
    float* out = (float*)d_out;

    cudaFuncSetAttribute(k_gemm, cudaFuncAttributeMaxDynamicSharedMemorySize, SMEM_TOTAL);

    k_xa<<<MROWS / 8, 256>>>(x, lA);
    k_conv_x_main<<<dim3(DIN / 2048, MROWS), 256>>>(x);
    k_conv_w_main<<<dim3(DIN / 2048, DOUT), 256>>>(W);
    k_edge_x<<<MROWS * 8 / 256, 256>>>();
    k_edge_w<<<DOUT * 8 / 256, 256>>>(lB);
    // grid: (rank 2) x (16 n-tiles) x (32 m-pairs) = 1024 CTAs, 512 clusters
    k_gemm<<<dim3(2, DOUT / TN, MROWS / 256), 256, SMEM_TOTAL>>>(b, out, x, W, lB);
}

// round 15
// speedup vs baseline: 2.7496x; 1.7716x over previous
#include <cuda_runtime.h>
#include <cuda_bf16.h>
#include <cuda_fp16.h>
#include <cstdint>
#include <cstddef>

#define MROWS 8192
#define DIN   4096
#define DOUT  4096
#define RNK   16
#define LDKX  4160
#define TM    128
#define TN    256
#define TK    64
#define NKC   65
#define NST   4
#define SCALING_F 2.0f

#if defined(__CUDA_ARCH__) && (defined(__CUDA_ARCH_FEAT_SM103_ALL) || \
    defined(__CUDA_ARCH_FEAT_SM100_ALL) || defined(__CUDA_ARCH_SPECIFIC__) || \
    defined(__CUDA_ARCH_FAMILY_SPECIFIC__))
#define TC5 1
#else
#define TC5 0
#endif

// Pre-swizzled tiled fp16 layouts (byte image == SMEM image):
//   g_xf: [mt=64][kc=65] blocks of 16384B (128 rows x 128B, SW128-permuted)
//   g_wf: [nt=16][kc=65] blocks of 32768B (256 rows x 128B, SW128-permuted)
__device__ __align__(128) __half g_xf[(size_t)MROWS * LDKX];
__device__ __align__(128) __half g_wf[(size_t)DOUT * LDKX];
__device__ __align__(128) float  g_xa[MROWS * RNK];

#define SWZ128(o) ((o) ^ (((o) >> 3) & 0x70))

__device__ __forceinline__ uint32_t smem_u32(const void* p) {
    uint32_t a;
    asm("{ .reg .u64 t; cvta.to.shared.u64 t, %1; cvt.u32.u64 %0, t; }" : "=r"(a) : "l"(p));
    return a;
}

#if TC5
__device__ __forceinline__ uint32_t elect_one() {
    uint32_t p;
    asm volatile("{\n\t.reg .pred p;\n\telect.sync _|p, 0xFFFFFFFF;\n\tselp.b32 %0, 1, 0, p;\n\t}" : "=r"(p));
    return p;
}
__device__ __forceinline__ void bulkcp(uint32_t dst, const void* src, uint32_t bytes, uint32_t mbar) {
    asm volatile(
        "cp.async.bulk.shared::cta.global.mbarrier::complete_tx::bytes [%0], [%1], %2, [%3];"
        :: "r"(dst), "l"(src), "r"(bytes), "r"(mbar) : "memory");
}
__device__ __forceinline__ void mbar_expect(uint32_t mbar, uint32_t bytes) {
    asm volatile("mbarrier.arrive.expect_tx.shared.b64 _, [%0], %1;"
                 :: "r"(mbar), "r"(bytes) : "memory");
}
__device__ __forceinline__ void mbar_wait(uint32_t mbar, uint32_t parity) {
    asm volatile(
        "{\n\t.reg .pred P;\n\t"
        "W_%=:\n\t"
        "mbarrier.try_wait.parity.acquire.cta.shared::cta.b64 P, [%0], %1, 0x989680;\n\t"
        "@P bra.uni D_%=;\n\t"
        "bra.uni W_%=;\n\t"
        "D_%=:\n\t}"
        :: "r"(mbar), "r"(parity) : "memory");
}
__device__ __forceinline__ uint64_t make_desc(uint32_t addr) {   // SW128 K-major
    const uint64_t base =
        (uint64_t(2) << 61) | (uint64_t(1) << 46) | (uint64_t(64) << 32) | (uint64_t(1) << 16);
    return base | ((uint64_t)(addr >> 4) & 0x3FFFULL);
}
// cg1: fp16 in (atype=btype=0), fp32 acc, M=128, N=256
#define MMA_IDESC ((1u << 4) | ((TN / 8) << 17) | ((TM / 16) << 24))

__device__ __forceinline__ void mma_ss(uint32_t d, uint64_t da, uint64_t db, uint32_t acc) {
    asm volatile(
        "{\n\t.reg .pred p;\n\t"
        "setp.ne.u32 p, %5, 0;\n\t"
        "tcgen05.mma.cta_group::1.kind::f16 [%0], %1, %2, %3, {%4, %4, %4, %4}, p;\n\t}"
        :: "r"(d), "l"(da), "l"(db), "r"(MMA_IDESC), "r"(0u), "r"(acc) : "memory");
}
__device__ __forceinline__ void ldtm32(uint32_t a, uint32_t* r) {
    asm volatile(
        "tcgen05.ld.sync.aligned.32x32b.x32.b32 "
        "{%0,%1,%2,%3,%4,%5,%6,%7,%8,%9,%10,%11,%12,%13,%14,%15,"
        "%16,%17,%18,%19,%20,%21,%22,%23,%24,%25,%26,%27,%28,%29,%30,%31}, [%32];"
        : "=r"(r[0]), "=r"(r[1]), "=r"(r[2]), "=r"(r[3]), "=r"(r[4]), "=r"(r[5]), "=r"(r[6]), "=r"(r[7]),
          "=r"(r[8]), "=r"(r[9]), "=r"(r[10]), "=r"(r[11]), "=r"(r[12]), "=r"(r[13]), "=r"(r[14]), "=r"(r[15]),
          "=r"(r[16]), "=r"(r[17]), "=r"(r[18]), "=r"(r[19]), "=r"(r[20]), "=r"(r[21]), "=r"(r[22]), "=r"(r[23]),
          "=r"(r[24]), "=r"(r[25]), "=r"(r[26]), "=r"(r[27]), "=r"(r[28]), "=r"(r[29]), "=r"(r[30]), "=r"(r[31])
        : "r"(a));
    asm volatile("tcgen05.wait::ld.sync.aligned;" ::: "memory");
}
#endif  // TC5

// ---- kernel 1: xa = x @ A^T ----
__global__ __launch_bounds__(256) void k_xa(const float* __restrict__ x,
                                            const float* __restrict__ A) {
    __shared__ float sA[16 * 512];
    const int tid = threadIdx.x, wid = tid >> 5, lid = tid & 31;
    const int m = blockIdx.x * 8 + wid;
    float acc[RNK];
#pragma unroll
    for (int r = 0; r < RNK; r++) acc[r] = 0.f;
    for (int k0 = 0; k0 < DIN; k0 += 512) {
        __syncthreads();
        for (int i = tid; i < 2048; i += 256) {
            int r = i >> 7, k4 = i & 127;
            ((float4*)sA)[i] = *(const float4*)(A + (size_t)r * DIN + k0 + k4 * 4);
        }
        __syncthreads();
        const float4* xr = (const float4*)(x + (size_t)m * DIN + k0);
#pragma unroll
        for (int j = 0; j < 4; j++) {
            const int k4 = lid + 32 * j;
            const float4 xv = xr[k4];
#pragma unroll
            for (int r = 0; r < RNK; r++) {
                float4 av = ((const float4*)sA)[r * 128 + k4];
                acc[r] = fmaf(xv.x, av.x, acc[r]);
                acc[r] = fmaf(xv.y, av.y, acc[r]);
                acc[r] = fmaf(xv.z, av.z, acc[r]);
                acc[r] = fmaf(xv.w, av.w, acc[r]);
            }
        }
    }
#pragma unroll
    for (int r = 0; r < RNK; r++) {
        float v = acc[r];
        v += __shfl_xor_sync(0xffffffffu, v, 16);
        v += __shfl_xor_sync(0xffffffffu, v, 8);
        v += __shfl_xor_sync(0xffffffffu, v, 4);
        v += __shfl_xor_sync(0xffffffffu, v, 2);
        v += __shfl_xor_sync(0xffffffffu, v, 1);
        if (lid == 0) g_xa[m * RNK + r] = v;
    }
}

// ---- fp16 convert, writing pre-swizzled tiled layout ----
__device__ __forceinline__ void cvt8(const float* v, void* dst) {
    uint32_t w[4];
#pragma unroll
    for (int k = 0; k < 4; k++) {
        __half2 h2 = __floats2half2_rn(v[2 * k], v[2 * k + 1]);
        w[k] = *(uint32_t*)&h2;
    }
    *(uint4*)dst = make_uint4(w[0], w[1], w[2], w[3]);
}
__global__ __launch_bounds__(256) void k_conv_x_main(const float* __restrict__ x) {
    const int m = blockIdx.y;
    const int c0 = (blockIdx.x * 256 + threadIdx.x) * 8;   // [0,4096)
    float v[8];
    *(float4*)v       = *(const float4*)(x + (size_t)m * DIN + c0);
    *(float4*)(v + 4) = *(const float4*)(x + (size_t)m * DIN + c0 + 4);
    const size_t blk = ((size_t)(m >> 7) * NKC + (c0 >> 6)) << 14;           // 16KB blocks
    const uint32_t sw = SWZ128((uint32_t)(((m & 127) << 7) + (((c0 >> 3) & 7) << 4)));
    cvt8(v, (char*)g_xf + blk + sw);
}
__global__ __launch_bounds__(256) void k_conv_w_main(const float* __restrict__ W) {
    const int n = blockIdx.y;
    const int c0 = (blockIdx.x * 256 + threadIdx.x) * 8;
    float v[8];
    *(float4*)v       = *(const float4*)(W + (size_t)n * DIN + c0);
    *(float4*)(v + 4) = *(const float4*)(W + (size_t)n * DIN + c0 + 4);
    const size_t blk = ((size_t)(n >> 8) * NKC + (c0 >> 6)) * 32768u;        // 32KB blocks
    const uint32_t sw = SWZ128((uint32_t)(((n & 255) << 7) + (((c0 >> 3) & 7) << 4)));
    cvt8(v, (char*)g_wf + blk + sw);
}
__global__ __launch_bounds__(256) void k_edge_x() {
    const int idx = blockIdx.x * 256 + threadIdx.x;
    const int row = idx >> 3, seg = idx & 7;
    float v[8];
#pragma unroll
    for (int j = 0; j < 8; j++) {
        const int c = seg * 8 + j;
        v[j] = (c < RNK) ? SCALING_F * g_xa[row * RNK + c] : 0.f;
    }
    const size_t blk = ((size_t)(row >> 7) * NKC + 64) << 14;
    const uint32_t sw = SWZ128((uint32_t)(((row & 127) << 7) + (seg << 4)));
    cvt8(v, (char*)g_xf + blk + sw);
}
__global__ __launch_bounds__(256) void k_edge_w(const float* __restrict__ lB) {
    const int idx = blockIdx.x * 256 + threadIdx.x;
    const int row = idx >> 3, seg = idx & 7;
    float v[8];
#pragma unroll
    for (int j = 0; j < 8; j++) {
        const int c = seg * 8 + j;
        v[j] = (c < RNK) ? lB[row * RNK + c] : 0.f;
    }
    const size_t blk = ((size_t)(row >> 8) * NKC + 64) * 32768u;
    const uint32_t sw = SWZ128((uint32_t)(((row & 255) << 7) + (seg << 4)));
    cvt8(v, (char*)g_wf + blk + sw);
}

// ---- main GEMM: cg1, fp16 single-term, 4-stage 48KB bulk-copy pipeline ----
// SMEM: [0] tmem ptr; full[4]@16..40; done[4]@48..72; bias@1024; stages@2048 (4 x 49152)
#define SMEM_BIAS   1024
#define SMEM_STAGE0 2048
#define STAGE_BYTES 49152
#define OFF_A 0
#define OFF_B 16384
#define SMEM_TOTAL (SMEM_STAGE0 + NST * STAGE_BYTES)

__global__ __launch_bounds__(256, 1)
void k_gemm(const float* __restrict__ bias, float* __restrict__ out,
            const float* __restrict__ x, const float* __restrict__ W,
            const float* __restrict__ lB) {
    extern __shared__ char smem[];
    const int tid = threadIdx.x;
    const int n0 = blockIdx.x * TN;
    const int m0 = blockIdx.y * TM;
#if TC5
    const uint32_t sbase = smem_u32(smem);
    const int wid = tid >> 5, lid = tid & 31;
    const uint32_t FUL = sbase + 16, DON = sbase + 48;

    if (wid == 0) {
        asm volatile("tcgen05.alloc.cta_group::1.sync.aligned.shared::cta.b32 [%0], %1;"
                     :: "r"(sbase), "r"(256u) : "memory");
        asm volatile("tcgen05.relinquish_alloc_permit.cta_group::1.sync.aligned;");
    }
    if (tid < 8)
        asm volatile("mbarrier.init.shared.b64 [%0], 1;" :: "r"(sbase + 16 + tid * 8) : "memory");
    ((float*)(smem + SMEM_BIAS))[tid] = bias[n0 + tid];
    __syncthreads();
    uint32_t tmem;
    asm volatile("ld.shared.b32 %0, [%1];" : "=r"(tmem) : "r"(sbase));

    if (wid == 0 && elect_one()) {
        const char* xf_t = (char*)g_xf + ((size_t)(m0 >> 7) * NKC << 14);
        const char* wf_t = (char*)g_wf + ((size_t)(n0 >> 8) * NKC) * 32768u;

        // prologue: chunks 0..2 -> stages 0..2
#pragma unroll
        for (int p = 0; p < NST - 1; p++) {
            const uint32_t st = sbase + SMEM_STAGE0 + p * STAGE_BYTES;
            const uint32_t fm = FUL + p * 8;
            mbar_expect(fm, STAGE_BYTES);
            bulkcp(st + OFF_A, xf_t + ((size_t)p << 14), 16384u, fm);
            bulkcp(st + OFF_B, wf_t + ((size_t)p << 15), 32768u, fm);
        }

#pragma unroll 1
        for (int kt = 0; kt < NKC; kt++) {
            const int s = kt & (NST - 1);
            if (kt + NST - 1 < NKC) {      // load chunk kt+3 into slot (kt+3)&3 == (kt-1)&3
                const int sl = (kt + NST - 1) & (NST - 1);
                if (kt >= 1)               // prior occupant chunk kt-1 must drain
                    mbar_wait(DON + sl * 8, (uint32_t)(((kt - 1) >> 2) & 1));
                const uint32_t st = sbase + SMEM_STAGE0 + sl * STAGE_BYTES;
                const uint32_t fm = FUL + sl * 8;
                mbar_expect(fm, STAGE_BYTES);
                bulkcp(st + OFF_A, xf_t + ((size_t)(kt + NST - 1) << 14), 16384u, fm);
                bulkcp(st + OFF_B, wf_t + ((size_t)(kt + NST - 1) << 15), 32768u, fm);
            }
            mbar_wait(FUL + s * 8, (uint32_t)((kt >> 2) & 1));   // stage data landed

            const uint32_t st = sbase + SMEM_STAGE0 + s * STAGE_BYTES;
            const uint64_t dA = make_desc(st + OFF_A);
            const uint64_t dB = make_desc(st + OFF_B);
#pragma unroll
            for (int ks = 0; ks < 4; ks++)
                mma_ss(tmem, dA + 2 * ks, dB + 2 * ks, (kt == 0 && ks == 0) ? 0u : 1u);
            asm volatile(
                "tcgen05.commit.cta_group::1.mbarrier::arrive::one.shared::cluster.b64 [%0];"
                :: "r"(DON + s * 8) : "memory");
        }
        // last chunk 64: slot 0, phase (64>>2)&1 = 0
        mbar_wait(DON, 0u);
    }
    __syncthreads();
    asm volatile("tcgen05.fence::after_thread_sync;" ::: "memory");

    const float* sbf = (const float*)(smem + SMEM_BIAS);
    const int rw = wid & 3, ch = wid >> 2;      // 8 warps: 4 row-groups x 2 col-halves
    float* orow = out + (size_t)(m0 + rw * 32 + lid) * DOUT + n0 + ch * 128;
#pragma unroll 1
    for (int c0 = 0; c0 < 128; c0 += 32) {
        uint32_t r[32];
        ldtm32(tmem + ch * 128 + c0, r);
#pragma unroll
        for (int j = 0; j < 32; j += 4) {
            float4 v;
            v.x = __uint_as_float(r[j + 0]) + sbf[ch * 128 + c0 + j + 0];
            v.y = __uint_as_float(r[j + 1]) + sbf[ch * 128 + c0 + j + 1];
            v.z = __uint_as_float(r[j + 2]) + sbf[ch * 128 + c0 + j + 2];
            v.w = __uint_as_float(r[j + 3]) + sbf[ch * 128 + c0 + j + 3];
            *(float4*)(orow + c0 + j) = v;
        }
    }
    __syncthreads();
    if (wid == 0)
        asm volatile("tcgen05.dealloc.cta_group::1.sync.aligned.b32 %0, %1;"
                     :: "r"(tmem), "r"(256u));
#else
    // ---------- fp32 SIMT fallback (base sm_103 target) ----------
    float* As = (float*)smem;            // [128][17]
    float* Bs = As + 128 * 17;           // [128][17]
    const int tx = tid & 15, ty = tid >> 4;
#pragma unroll 1
    for (int nh = 0; nh < 2; nh++) {
        const int nb = n0 + nh * 128;
        float acc[8][8];
#pragma unroll
        for (int i = 0; i < 8; i++)
#pragma unroll
            for (int j = 0; j < 8; j++) acc[i][j] = 0.f;
#pragma unroll 1
        for (int k0 = 0; k0 < DIN; k0 += 16) {
            __syncthreads();
            for (int i = tid; i < 128 * 16; i += 256) {
                const int m = i >> 4, kk = i & 15;
                As[m * 17 + kk] = x[(size_t)(m0 + m) * DIN + k0 + kk];
                Bs[m * 17 + kk] = W[(size_t)(nb + m) * DIN + k0 + kk];
            }
            __syncthreads();
#pragma unroll
            for (int kk = 0; kk < 16; kk++) {
                float ra[8], rb[8];
#pragma unroll
                for (int j = 0; j < 8; j++) {
                    ra[j] = As[(ty * 8 + j) * 17 + kk];
                    rb[j] = Bs[(tx * 8 + j) * 17 + kk];
                }
#pragma unroll
                for (int i = 0; i < 8; i++)
#pragma unroll
                    for (int j = 0; j < 8; j++)
                        acc[i][j] = fmaf(ra[i], rb[j], acc[i][j]);
            }
        }
#pragma unroll
        for (int i = 0; i < 8; i++) {
            const int m = m0 + ty * 8 + i;
            const float* xar = g_xa + m * RNK;
#pragma unroll
            for (int j = 0; j < 8; j++) {
                const int n = nb + tx * 8 + j;
                float l = 0.f;
#pragma unroll
                for (int r = 0; r < RNK; r++) l = fmaf(xar[r], lB[n * RNK + r], l);
                out[(size_t)m * DOUT + n] = acc[i][j] + bias[n] + SCALING_F * l;
            }
        }
        __syncthreads();
    }
#endif
}

extern "C" void kernel_launch(void* const* d_in, const int* in_sizes, int n_in,
                              void* d_out, int out_size) {
    const float* x  = (const float*)d_in[0];
    const float* W  = (const float*)d_in[1];
    const float* b  = (const float*)d_in[2];
    const float* lA = (const float*)d_in[3];
    const float* lB = (const float*)d_in[4];
    float* out = (float*)d_out;

    cudaFuncSetAttribute(k_gemm, cudaFuncAttributeMaxDynamicSharedMemorySize, SMEM_TOTAL);

    k_xa<<<MROWS / 8, 256>>>(x, lA);
    k_conv_x_main<<<dim3(DIN / 2048, MROWS), 256>>>(x);
    k_conv_w_main<<<dim3(DIN / 2048, DOUT), 256>>>(W);
    k_edge_x<<<MROWS * 8 / 256, 256>>>();
    k_edge_w<<<DOUT * 8 / 256, 256>>>(lB);
    k_gemm<<<dim3(DOUT / TN, MROWS / TM), 256, SMEM_TOTAL>>>(b, out, x, W, lB);
}

// round 16
// speedup vs baseline: 2.8235x; 1.0269x over previous
#include <cuda_runtime.h>
#include <cuda_bf16.h>
#include <cuda_fp16.h>
#include <cstdint>
#include <cstddef>

#define MROWS 8192
#define DIN   4096
#define DOUT  4096
#define RNK   16
#define LDKX  4160
#define TM    256          // per CTA, as 2x M=128 accumulators
#define TN    256
#define TK    64
#define NKC   65
#define NST   3
#define SCALING_F 2.0f

#if defined(__CUDA_ARCH__) && (defined(__CUDA_ARCH_FEAT_SM103_ALL) || \
    defined(__CUDA_ARCH_FEAT_SM100_ALL) || defined(__CUDA_ARCH_SPECIFIC__) || \
    defined(__CUDA_ARCH_FAMILY_SPECIFIC__))
#define TC5 1
#else
#define TC5 0
#endif

// Pre-swizzled tiled fp16 layouts (byte image == SMEM image):
//   g_xf: [mt=32][kc=65] blocks of 32768B (256 rows x 128B, SW128-permuted)
//   g_wf: [nt=16][kc=65] blocks of 32768B (256 rows x 128B, SW128-permuted)
__device__ __align__(128) __half g_xf[(size_t)MROWS * LDKX];
__device__ __align__(128) __half g_wf[(size_t)DOUT * LDKX];
__device__ __align__(128) float  g_xa[MROWS * RNK];

#define SWZ128(o) ((o) ^ (((o) >> 3) & 0x70))

__device__ __forceinline__ uint32_t smem_u32(const void* p) {
    uint32_t a;
    asm("{ .reg .u64 t; cvta.to.shared.u64 t, %1; cvt.u32.u64 %0, t; }" : "=r"(a) : "l"(p));
    return a;
}

#if TC5
__device__ __forceinline__ uint32_t elect_one() {
    uint32_t p;
    asm volatile("{\n\t.reg .pred p;\n\telect.sync _|p, 0xFFFFFFFF;\n\tselp.b32 %0, 1, 0, p;\n\t}" : "=r"(p));
    return p;
}
__device__ __forceinline__ void bulkcp(uint32_t dst, const void* src, uint32_t bytes, uint32_t mbar) {
    asm volatile(
        "cp.async.bulk.shared::cta.global.mbarrier::complete_tx::bytes [%0], [%1], %2, [%3];"
        :: "r"(dst), "l"(src), "r"(bytes), "r"(mbar) : "memory");
}
__device__ __forceinline__ void mbar_expect(uint32_t mbar, uint32_t bytes) {
    asm volatile("mbarrier.arrive.expect_tx.shared.b64 _, [%0], %1;"
                 :: "r"(mbar), "r"(bytes) : "memory");
}
__device__ __forceinline__ void mbar_wait(uint32_t mbar, uint32_t parity) {
    asm volatile(
        "{\n\t.reg .pred P;\n\t"
        "W_%=:\n\t"
        "mbarrier.try_wait.parity.acquire.cta.shared::cta.b64 P, [%0], %1, 0x989680;\n\t"
        "@P bra.uni D_%=;\n\t"
        "bra.uni W_%=;\n\t"
        "D_%=:\n\t}"
        :: "r"(mbar), "r"(parity) : "memory");
}
__device__ __forceinline__ uint64_t make_desc(uint32_t addr) {   // SW128 K-major
    const uint64_t base =
        (uint64_t(2) << 61) | (uint64_t(1) << 46) | (uint64_t(64) << 32) | (uint64_t(1) << 16);
    return base | ((uint64_t)(addr >> 4) & 0x3FFFULL);
}
// cg1: fp16 in, fp32 acc, M=128 per accumulator, N=256
#define MMA_IDESC ((1u << 4) | ((TN / 8) << 17) | ((128 / 16) << 24))

__device__ __forceinline__ void mma_ss(uint32_t d, uint64_t da, uint64_t db, uint32_t acc) {
    asm volatile(
        "{\n\t.reg .pred p;\n\t"
        "setp.ne.u32 p, %5, 0;\n\t"
        "tcgen05.mma.cta_group::1.kind::f16 [%0], %1, %2, %3, {%4, %4, %4, %4}, p;\n\t}"
        :: "r"(d), "l"(da), "l"(db), "r"(MMA_IDESC), "r"(0u), "r"(acc) : "memory");
}
__device__ __forceinline__ void ldtm32(uint32_t a, uint32_t* r) {
    asm volatile(
        "tcgen05.ld.sync.aligned.32x32b.x32.b32 "
        "{%0,%1,%2,%3,%4,%5,%6,%7,%8,%9,%10,%11,%12,%13,%14,%15,"
        "%16,%17,%18,%19,%20,%21,%22,%23,%24,%25,%26,%27,%28,%29,%30,%31}, [%32];"
        : "=r"(r[0]), "=r"(r[1]), "=r"(r[2]), "=r"(r[3]), "=r"(r[4]), "=r"(r[5]), "=r"(r[6]), "=r"(r[7]),
          "=r"(r[8]), "=r"(r[9]), "=r"(r[10]), "=r"(r[11]), "=r"(r[12]), "=r"(r[13]), "=r"(r[14]), "=r"(r[15]),
          "=r"(r[16]), "=r"(r[17]), "=r"(r[18]), "=r"(r[19]), "=r"(r[20]), "=r"(r[21]), "=r"(r[22]), "=r"(r[23]),
          "=r"(r[24]), "=r"(r[25]), "=r"(r[26]), "=r"(r[27]), "=r"(r[28]), "=r"(r[29]), "=r"(r[30]), "=r"(r[31])
        : "r"(a));
    asm volatile("tcgen05.wait::ld.sync.aligned;" ::: "memory");
}
#endif  // TC5

// ---- kernel 1: xa = x @ A^T ----
__global__ __launch_bounds__(256) void k_xa(const float* __restrict__ x,
                                            const float* __restrict__ A) {
    __shared__ float sA[16 * 512];
    const int tid = threadIdx.x, wid = tid >> 5, lid = tid & 31;
    const int m = blockIdx.x * 8 + wid;
    float acc[RNK];
#pragma unroll
    for (int r = 0; r < RNK; r++) acc[r] = 0.f;
    for (int k0 = 0; k0 < DIN; k0 += 512) {
        __syncthreads();
        for (int i = tid; i < 2048; i += 256) {
            int r = i >> 7, k4 = i & 127;
            ((float4*)sA)[i] = *(const float4*)(A + (size_t)r * DIN + k0 + k4 * 4);
        }
        __syncthreads();
        const float4* xr = (const float4*)(x + (size_t)m * DIN + k0);
#pragma unroll
        for (int j = 0; j < 4; j++) {
            const int k4 = lid + 32 * j;
            const float4 xv = xr[k4];
#pragma unroll
            for (int r = 0; r < RNK; r++) {
                float4 av = ((const float4*)sA)[r * 128 + k4];
                acc[r] = fmaf(xv.x, av.x, acc[r]);
                acc[r] = fmaf(xv.y, av.y, acc[r]);
                acc[r] = fmaf(xv.z, av.z, acc[r]);
                acc[r] = fmaf(xv.w, av.w, acc[r]);
            }
        }
    }
#pragma unroll
    for (int r = 0; r < RNK; r++) {
        float v = acc[r];
        v += __shfl_xor_sync(0xffffffffu, v, 16);
        v += __shfl_xor_sync(0xffffffffu, v, 8);
        v += __shfl_xor_sync(0xffffffffu, v, 4);
        v += __shfl_xor_sync(0xffffffffu, v, 2);
        v += __shfl_xor_sync(0xffffffffu, v, 1);
        if (lid == 0) g_xa[m * RNK + r] = v;
    }
}

// ---- fp16 convert, writing pre-swizzled tiled layout (32KB / 256-row blocks) ----
__device__ __forceinline__ void cvt8(const float* v, void* dst) {
    uint32_t w[4];
#pragma unroll
    for (int k = 0; k < 4; k++) {
        __half2 h2 = __floats2half2_rn(v[2 * k], v[2 * k + 1]);
        w[k] = *(uint32_t*)&h2;
    }
    *(uint4*)dst = make_uint4(w[0], w[1], w[2], w[3]);
}
__global__ __launch_bounds__(256) void k_conv_x_main(const float* __restrict__ x) {
    const int m = blockIdx.y;
    const int c0 = (blockIdx.x * 256 + threadIdx.x) * 8;   // [0,4096)
    float v[8];
    *(float4*)v       = *(const float4*)(x + (size_t)m * DIN + c0);
    *(float4*)(v + 4) = *(const float4*)(x + (size_t)m * DIN + c0 + 4);
    const size_t blk = ((size_t)(m >> 8) * NKC + (c0 >> 6)) * 32768u;
    const uint32_t sw = SWZ128((uint32_t)(((m & 255) << 7) + (((c0 >> 3) & 7) << 4)));
    cvt8(v, (char*)g_xf + blk + sw);
}
__global__ __launch_bounds__(256) void k_conv_w_main(const float* __restrict__ W) {
    const int n = blockIdx.y;
    const int c0 = (blockIdx.x * 256 + threadIdx.x) * 8;
    float v[8];
    *(float4*)v       = *(const float4*)(W + (size_t)n * DIN + c0);
    *(float4*)(v + 4) = *(const float4*)(W + (size_t)n * DIN + c0 + 4);
    const size_t blk = ((size_t)(n >> 8) * NKC + (c0 >> 6)) * 32768u;
    const uint32_t sw = SWZ128((uint32_t)(((n & 255) << 7) + (((c0 >> 3) & 7) << 4)));
    cvt8(v, (char*)g_wf + blk + sw);
}
__global__ __launch_bounds__(256) void k_edge_x() {
    const int idx = blockIdx.x * 256 + threadIdx.x;
    const int row = idx >> 3, seg = idx & 7;
    float v[8];
#pragma unroll
    for (int j = 0; j < 8; j++) {
        const int c = seg * 8 + j;
        v[j] = (c < RNK) ? SCALING_F * g_xa[row * RNK + c] : 0.f;
    }
    const size_t blk = ((size_t)(row >> 8) * NKC + 64) * 32768u;
    const uint32_t sw = SWZ128((uint32_t)(((row & 255) << 7) + (seg << 4)));
    cvt8(v, (char*)g_xf + blk + sw);
}
__global__ __launch_bounds__(256) void k_edge_w(const float* __restrict__ lB) {
    const int idx = blockIdx.x * 256 + threadIdx.x;
    const int row = idx >> 3, seg = idx & 7;
    float v[8];
#pragma unroll
    for (int j = 0; j < 8; j++) {
        const int c = seg * 8 + j;
        v[j] = (c < RNK) ? lB[row * RNK + c] : 0.f;
    }
    const size_t blk = ((size_t)(row >> 8) * NKC + 64) * 32768u;
    const uint32_t sw = SWZ128((uint32_t)(((row & 255) << 7) + (seg << 4)));
    cvt8(v, (char*)g_wf + blk + sw);
}

// ---- main GEMM: cg1, fp16, 256x256 tile (2 TMEM accumulators), 3-stage 64KB ----
// SMEM: [0] tmem ptr; full[3]@16..32; done[3]@48..64; bias@1024; stages@2048 (3 x 65536)
#define SMEM_BIAS   1024
#define SMEM_STAGE0 2048
#define STAGE_BYTES 65536
#define OFF_A 0
#define OFF_B 32768
#define SMEM_TOTAL (SMEM_STAGE0 + NST * STAGE_BYTES)

__global__ __launch_bounds__(256, 1)
void k_gemm(const float* __restrict__ bias, float* __restrict__ out,
            const float* __restrict__ x, const float* __restrict__ W,
            const float* __restrict__ lB) {
    extern __shared__ char smem[];
    const int tid = threadIdx.x;
    const int n0 = blockIdx.x * TN;
    const int m0 = blockIdx.y * TM;
#if TC5
    const uint32_t sbase = smem_u32(smem);
    const int wid = tid >> 5, lid = tid & 31;
    const uint32_t FUL = sbase + 16, DON = sbase + 48;

    if (wid == 0) {
        asm volatile("tcgen05.alloc.cta_group::1.sync.aligned.shared::cta.b32 [%0], %1;"
                     :: "r"(sbase), "r"(512u) : "memory");
        asm volatile("tcgen05.relinquish_alloc_permit.cta_group::1.sync.aligned;");
    }
    if (tid < NST)
        asm volatile("mbarrier.init.shared.b64 [%0], 1;" :: "r"(FUL + tid * 8) : "memory");
    else if (tid < 2 * NST)
        asm volatile("mbarrier.init.shared.b64 [%0], 1;" :: "r"(DON + (tid - NST) * 8) : "memory");
    ((float*)(smem + SMEM_BIAS))[tid] = bias[n0 + tid];
    __syncthreads();
    uint32_t tmem;
    asm volatile("ld.shared.b32 %0, [%1];" : "=r"(tmem) : "r"(sbase));

    if (wid == 0 && elect_one()) {
        const char* xf_t = (char*)g_xf + ((size_t)(m0 >> 8) * NKC) * 32768u;
        const char* wf_t = (char*)g_wf + ((size_t)(n0 >> 8) * NKC) * 32768u;

        // prologue: chunks 0..1 -> stages 0..1
#pragma unroll
        for (int p = 0; p < NST - 1; p++) {
            const uint32_t st = sbase + SMEM_STAGE0 + p * STAGE_BYTES;
            const uint32_t fm = FUL + p * 8;
            mbar_expect(fm, STAGE_BYTES);
            bulkcp(st + OFF_A, xf_t + ((size_t)p << 15), 32768u, fm);
            bulkcp(st + OFF_B, wf_t + ((size_t)p << 15), 32768u, fm);
        }

#pragma unroll 1
        for (int kt = 0; kt < NKC; kt++) {
            const int s = kt % NST;
            const uint32_t ph = (uint32_t)((kt / NST) & 1);
            if (kt + NST - 1 < NKC) {      // load chunk kt+2 into slot (kt+2)%3 == (kt-1)%3
                const int sl = (kt + NST - 1) % NST;
                if (kt >= 1)               // prior occupant chunk kt-1 must drain
                    mbar_wait(DON + sl * 8, (uint32_t)(((kt - 1) / NST) & 1));
                const uint32_t st = sbase + SMEM_STAGE0 + sl * STAGE_BYTES;
                const uint32_t fm = FUL + sl * 8;
                mbar_expect(fm, STAGE_BYTES);
                bulkcp(st + OFF_A, xf_t + ((size_t)(kt + NST - 1) << 15), 32768u, fm);
                bulkcp(st + OFF_B, wf_t + ((size_t)(kt + NST - 1) << 15), 32768u, fm);
            }
            mbar_wait(FUL + s * 8, ph);    // stage data landed

            const uint32_t st = sbase + SMEM_STAGE0 + s * STAGE_BYTES;
            const uint64_t dA = make_desc(st + OFF_A);
            const uint64_t dB = make_desc(st + OFF_B);
            const uint32_t first = (kt == 0) ? 0u : 1u;
#pragma unroll
            for (int h = 0; h < 2; h++) {  // two M=128 halves -> two accumulators
                const uint32_t d = tmem + h * 256;
                const uint64_t ao = (uint64_t)(h * 1024);   // 128 rows * 128B / 16
#pragma unroll
                for (int ks = 0; ks < 4; ks++)
                    mma_ss(d, dA + ao + 2 * ks, dB + 2 * ks, (first == 0u && ks == 0) ? 0u : 1u);
            }
            asm volatile(
                "tcgen05.commit.cta_group::1.mbarrier::arrive::one.shared::cluster.b64 [%0];"
                :: "r"(DON + s * 8) : "memory");
        }
        // last chunk 64: slot 64%3=1, phase (64/3)&1=1
        mbar_wait(DON + 8, 1u);
    }
    __syncthreads();
    asm volatile("tcgen05.fence::after_thread_sync;" ::: "memory");

    const float* sbf = (const float*)(smem + SMEM_BIAS);
    const int half = wid >> 2, rw = wid & 3;    // 8 warps = 2 halves x 4 row-groups
    const uint32_t acc_base = tmem + half * 256;
    float* orow = out + (size_t)(m0 + half * 128 + rw * 32 + lid) * DOUT + n0;
#pragma unroll 1
    for (int c0 = 0; c0 < TN; c0 += 32) {
        uint32_t r[32];
        ldtm32(acc_base + c0, r);
#pragma unroll
        for (int j = 0; j < 32; j += 4) {
            float4 v;
            v.x = __uint_as_float(r[j + 0]) + sbf[c0 + j + 0];
            v.y = __uint_as_float(r[j + 1]) + sbf[c0 + j + 1];
            v.z = __uint_as_float(r[j + 2]) + sbf[c0 + j + 2];
            v.w = __uint_as_float(r[j + 3]) + sbf[c0 + j + 3];
            *(float4*)(orow + c0 + j) = v;
        }
    }
    __syncthreads();
    if (wid == 0)
        asm volatile("tcgen05.dealloc.cta_group::1.sync.aligned.b32 %0, %1;"
                     :: "r"(tmem), "r"(512u));
#else
    // ---------- fp32 SIMT fallback (base sm_103 target) ----------
    float* As = (float*)smem;            // [128][17]
    float* Bs = As + 128 * 17;           // [128][17]
    const int tx = tid & 15, ty = tid >> 4;
#pragma unroll 1
    for (int mh = 0; mh < 2; mh++) {
        const int mb = m0 + mh * 128;
#pragma unroll 1
        for (int nh = 0; nh < 2; nh++) {
            const int nb = n0 + nh * 128;
            float acc[8][8];
#pragma unroll
            for (int i = 0; i < 8; i++)
#pragma unroll
                for (int j = 0; j < 8; j++) acc[i][j] = 0.f;
#pragma unroll 1
            for (int k0 = 0; k0 < DIN; k0 += 16) {
                __syncthreads();
                for (int i = tid; i < 128 * 16; i += 256) {
                    const int m = i >> 4, kk = i & 15;
                    As[m * 17 + kk] = x[(size_t)(mb + m) * DIN + k0 + kk];
                    Bs[m * 17 + kk] = W[(size_t)(nb + m) * DIN + k0 + kk];
                }
                __syncthreads();
#pragma unroll
                for (int kk = 0; kk < 16; kk++) {
                    float ra[8], rb[8];
#pragma unroll
                    for (int j = 0; j < 8; j++) {
                        ra[j] = As[(ty * 8 + j) * 17 + kk];
                        rb[j] = Bs[(tx * 8 + j) * 17 + kk];
                    }
#pragma unroll
                    for (int i = 0; i < 8; i++)
#pragma unroll
                        for (int j = 0; j < 8; j++)
                            acc[i][j] = fmaf(ra[i], rb[j], acc[i][j]);
                }
            }
#pragma unroll
            for (int i = 0; i < 8; i++) {
                const int m = mb + ty * 8 + i;
                const float* xar = g_xa + m * RNK;
#pragma unroll
                for (int j = 0; j < 8; j++) {
                    const int n = nb + tx * 8 + j;
                    float l = 0.f;
#pragma unroll
                    for (int r = 0; r < RNK; r++) l = fmaf(xar[r], lB[n * RNK + r], l);
                    out[(size_t)m * DOUT + n] = acc[i][j] + bias[n] + SCALING_F * l;
                }
            }
            __syncthreads();
        }
    }
#endif
}

extern "C" void kernel_launch(void* const* d_in, const int* in_sizes, int n_in,
                              void* d_out, int out_size) {
    const float* x  = (const float*)d_in[0];
    const float* W  = (const float*)d_in[1];
    const float* b  = (const float*)d_in[2];
    const float* lA = (const float*)d_in[3];
    const float* lB = (const float*)d_in[4];
    float* out = (float*)d_out;

    cudaFuncSetAttribute(k_gemm, cudaFuncAttributeMaxDynamicSharedMemorySize, SMEM_TOTAL);

    k_xa<<<MROWS / 8, 256>>>(x, lA);
    k_conv_x_main<<<dim3(DIN / 2048, MROWS), 256>>>(x);
    k_conv_w_main<<<dim3(DIN / 2048, DOUT), 256>>>(W);
    k_edge_x<<<MROWS * 8 / 256, 256>>>();
    k_edge_w<<<DOUT * 8 / 256, 256>>>(lB);
    k_gemm<<<dim3(DOUT / TN, MROWS / TM), 256, SMEM_TOTAL>>>(b, out, x, W, lB);
}